// round 16
// baseline (speedup 1.0000x reference)
#include <cuda_runtime.h>
#include <math.h>

#define BB 2
#define NN 512
#define DIN 512
#define DM 256
#define C2LOG2E 2.885390081777927f   // 2*log2(e)

typedef unsigned long long ull;

// scratch (static device globals — no allocation)
__device__ float g_h[BB * NN * DM];    // h[b][n][d] = tanh(x@Wx+bx)
__device__ float g_p[BB * NN * DM];    // P row-major: exp2(c*(u+bp))
__device__ float g_qt[BB * DM * NN];   // Q transposed: exp2(-c*u)[b][d][n]

__device__ __forceinline__ float ex2_fast(float x) {
    float y; asm("ex2.approx.f32 %0, %1;" : "=f"(y) : "f"(x)); return y;
}
__device__ __forceinline__ float rcp_fast(float x) {
    float y; asm("rcp.approx.f32 %0, %1;" : "=f"(y) : "f"(x)); return y;
}
// ---- packed f32x2 helpers (Blackwell FFMA2 path) ----
__device__ __forceinline__ ull pack2(float lo, float hi) {
    ull r; asm("mov.b64 %0, {%1, %2};" : "=l"(r) : "f"(lo), "f"(hi)); return r;
}
__device__ __forceinline__ void unpack2(ull v, float& lo, float& hi) {
    asm("mov.b64 {%0, %1}, %2;" : "=f"(lo), "=f"(hi) : "l"(v));
}
__device__ __forceinline__ ull fma2(ull a, ull b, ull c) {
    ull d; asm("fma.rn.f32x2 %0, %1, %2, %3;" : "=l"(d) : "l"(a), "l"(b), "l"(c)); return d;
}
__device__ __forceinline__ ull mul2(ull a, ull b) {
    ull d; asm("mul.rn.f32x2 %0, %1, %2;" : "=l"(d) : "l"(a), "l"(b)); return d;
}
__device__ __forceinline__ ull add2(ull a, ull b) {
    ull d; asm("add.rn.f32x2 %0, %1, %2;" : "=l"(d) : "l"(a), "l"(b)); return d;
}

// ---------------------------------------------------------------------------
// Kernel A (f32x2, 8 chains): h = tanh(x @ Wx + bx), P/Q projections.
// 4 rows/block, thread owns col-pair; K split 8-way; dual accumulators
// (even-k / odd-k) restore 8 independent fma2 chains.
// grid 256 x 1024 threads.
// ---------------------------------------------------------------------------
__global__ __launch_bounds__(1024) void kA(const float* __restrict__ x,
                                           const float* __restrict__ pos,
                                           const float* __restrict__ Wx,
                                           const float* __restrict__ bx,
                                           const float* __restrict__ Wp,
                                           const float* __restrict__ bp) {
    __shared__ ull s_x2[DIN][4];            // x broadcast pairs, 16KB
    __shared__ ull s_part[8][4][DM / 2];    // packed partials, 32KB
    const int t = threadIdx.x;
    const int row0 = blockIdx.x * 4;
    const int cp = t & 127;
    const int c2 = cp * 2;
    const int kq = t >> 7;
    const int b = row0 / NN;
    const int n0 = row0 % NN;

    if (t < DM) {
        const float w0 = Wp[0 * DM + t], w1 = Wp[1 * DM + t];
        const float w2 = Wp[2 * DM + t], w3 = Wp[3 * DM + t];
        const float bpv = bp[t];
#pragma unroll
        for (int r = 0; r < 4; r++) {
            const float* p = pos + (row0 + r) * 4;
            float u = p[0] * w0 + p[1] * w1 + p[2] * w2 + p[3] * w3;
            g_p[(row0 + r) * DM + t] = ex2_fast(C2LOG2E * (u + bpv));
            g_qt[(b * DM + t) * NN + n0 + r] = ex2_fast(-C2LOG2E * u);
        }
    }

    for (int e = t; e < DIN * 4; e += 1024) {
        int r = e >> 9, cc = e & (DIN - 1);
        float v = x[(row0 + r) * DIN + cc];
        s_x2[cc][r] = pack2(v, v);
    }
    __syncthreads();

    // dual accumulators: A = even k, B = odd k  (8 independent fma2 chains)
    ull a0A = 0, a1A = 0, a2A = 0, a3A = 0;
    ull a0B = 0, a1B = 0, a2B = 0, a3B = 0;
    const int kb = kq << 6;
#pragma unroll 4
    for (int k = 0; k < 64; k += 2) {
        ull wv0 = *(const ull*)&Wx[(kb + k) * DM + c2];         // LDG.64
        ull wv1 = *(const ull*)&Wx[(kb + k + 1) * DM + c2];
        ulonglong2 xA0 = *(const ulonglong2*)&s_x2[kb + k][0];  // LDS.128
        ulonglong2 xB0 = *(const ulonglong2*)&s_x2[kb + k][2];
        ulonglong2 xA1 = *(const ulonglong2*)&s_x2[kb + k + 1][0];
        ulonglong2 xB1 = *(const ulonglong2*)&s_x2[kb + k + 1][2];
        a0A = fma2(xA0.x, wv0, a0A);  a0B = fma2(xA1.x, wv1, a0B);
        a1A = fma2(xA0.y, wv0, a1A);  a1B = fma2(xA1.y, wv1, a1B);
        a2A = fma2(xB0.x, wv0, a2A);  a2B = fma2(xB1.x, wv1, a2B);
        a3A = fma2(xB0.y, wv0, a3A);  a3B = fma2(xB1.y, wv1, a3B);
    }
    s_part[kq][0][cp] = add2(a0A, a0B);
    s_part[kq][1][cp] = add2(a1A, a1B);
    s_part[kq][2][cp] = add2(a2A, a2B);
    s_part[kq][3][cp] = add2(a3A, a3B);
    __syncthreads();

    if (t < 512) {
        const int r = t >> 7;
        const int p = t & 127;
        ull s = s_part[0][r][p];
#pragma unroll
        for (int g = 1; g < 8; g++) s = add2(s, s_part[g][r][p]);
        float lo, hi;
        unpack2(s, lo, hi);
        g_h[(row0 + r) * DM + 2 * p]     = tanhf(lo + bx[2 * p]);
        g_h[(row0 + r) * DM + 2 * p + 1] = tanhf(hi + bx[2 * p + 1]);
    }
}

// ---------------------------------------------------------------------------
// Kernel Score (R14 best, unchanged): f32x2 packed, 4 rows x 128 j per block,
// d split 8-way. grid = 1024 blocks, 512 threads.
// ---------------------------------------------------------------------------
__global__ __launch_bounds__(512) void kScore(const float* __restrict__ w,
                                              float* __restrict__ attn_out) {
    __shared__ ull s_pib[DM][4];        // P broadcast pairs, 8KB
    __shared__ ull s_wn2[DM];           // (-2w,-2w), 2KB
    __shared__ ull s_part[7][4][64];    // dq=1..7 partials, 14KB
    __shared__ float s_W;

    const int t   = threadIdx.x;
    const int tj2 = t & 63;
    const int dq  = t >> 6;
    const int jt  = blockIdx.x & 3;
    const int it  = blockIdx.x >> 2;
    const int b   = it / (NN / 4);
    const int i0  = (it % (NN / 4)) * 4;
    const int j0  = jt * 128 + tj2 * 2;

    if (t < DM) {
        float wv = -2.0f * w[t];
        s_wn2[t] = pack2(wv, wv);
    }
    if (t < 32) {
        float s = 0.f;
#pragma unroll
        for (int k = 0; k < 8; k++) s += w[t + 32 * k];
#pragma unroll
        for (int o = 16; o; o >>= 1) s += __shfl_xor_sync(0xffffffffu, s, o);
        if (t == 0) s_W = s;
    }
    {
        const float* prow = g_p + (b * NN + i0) * DM;
        for (int e = t; e < 4 * DM; e += 512) {
            int r = e >> 8, d = e & (DM - 1);
            float v = prow[r * DM + d];
            s_pib[d][r] = pack2(v, v);
        }
    }
    __syncthreads();

    const ull ONE2 = pack2(1.0f, 1.0f);
    ull acc0 = 0, acc1 = 0, acc2 = 0, acc3 = 0;
    const float* qp = g_qt + b * DM * NN + j0;
    const int db = dq << 5;
    ull qbuf[4];
#pragma unroll
    for (int p = 0; p < 4; p++) qbuf[p] = *(const ull*)(qp + (db + p) * NN);

    for (int d0 = db; d0 < db + 32; d0 += 4) {
        ull qc[4];
#pragma unroll
        for (int p = 0; p < 4; p++) qc[p] = qbuf[p];
        if (d0 + 4 < db + 32) {
#pragma unroll
            for (int p = 0; p < 4; p++) qbuf[p] = *(const ull*)(qp + (d0 + 4 + p) * NN);
        }
#pragma unroll
        for (int dd = 0; dd < 4; dd++) {
            const int d = d0 + dd;
            const ull wn2 = s_wn2[d];
            ulonglong2 piA = *(const ulonglong2*)&s_pib[d][0];
            ulonglong2 piB = *(const ulonglong2*)&s_pib[d][2];
            const ull qj2 = qc[dd];
            ull de0 = fma2(piA.x, qj2, ONE2);
            ull de1 = fma2(piA.y, qj2, ONE2);
            ull de2 = fma2(piB.x, qj2, ONE2);
            ull de3 = fma2(piB.y, qj2, ONE2);
            ull p01 = mul2(de0, de1);
            ull p23 = mul2(de2, de3);
            ull tot = mul2(p01, p23);
            float tl, th;
            unpack2(tot, tl, th);
            ull r2 = pack2(rcp_fast(tl), rcp_fast(th));
            ull i01 = mul2(r2, p23);
            ull i23 = mul2(r2, p01);
            ull w01 = mul2(wn2, i01);
            ull w23 = mul2(wn2, i23);
            acc0 = fma2(w01, de1, acc0);
            acc1 = fma2(w01, de0, acc1);
            acc2 = fma2(w23, de3, acc2);
            acc3 = fma2(w23, de2, acc3);
        }
    }
    if (dq) {
        s_part[dq - 1][0][tj2] = acc0;
        s_part[dq - 1][1][tj2] = acc1;
        s_part[dq - 1][2][tj2] = acc2;
        s_part[dq - 1][3][tj2] = acc3;
    }
    __syncthreads();
    if (dq == 0) {
        const ull W2 = pack2(s_W, s_W);
#pragma unroll
        for (int g = 0; g < 7; g++) {
            acc0 = add2(acc0, s_part[g][0][tj2]);
            acc1 = add2(acc1, s_part[g][1][tj2]);
            acc2 = add2(acc2, s_part[g][2][tj2]);
            acc3 = add2(acc3, s_part[g][3][tj2]);
        }
        float* arow = attn_out + (b * NN + i0) * NN + j0;
        *(ull*)&arow[0 * NN] = add2(acc0, W2);
        *(ull*)&arow[1 * NN] = add2(acc1, W2);
        *(ull*)&arow[2 * NN] = add2(acc2, W2);
        *(ull*)&arow[3 * NN] = add2(acc3, W2);
    }
}

// ---------------------------------------------------------------------------
// Kernel SO (f32x2, 8 chains): masked softmax + output GEMM.
// Thread owns d-col pair x j-group of 64; dual accumulators (h0/h1 chains).
// grid = 256 blocks, 1024 threads.
// ---------------------------------------------------------------------------
__global__ __launch_bounds__(1024) void kSO(const int* __restrict__ mask,
                                            float* __restrict__ out,
                                            float* __restrict__ attn_out) {
    __shared__ float s_attn[4][NN];          // 8KB
    __shared__ ull s_attn2[4][NN];           // prob broadcast pairs, 16KB
    __shared__ ull s_part[8][4][DM / 2];     // packed partials, 32KB

    const int t = threadIdx.x;
    const int blk = blockIdx.x;
    const int b = blk / (NN / 4);
    const int i0 = (blk % (NN / 4)) * 4;

    {
        const float4* src = (const float4*)(attn_out + (b * NN + i0) * NN);
        float4* dst = (float4*)&s_attn[0][0];
        for (int e = t; e < 4 * NN / 4; e += 1024) dst[e] = src[e];
    }
    __syncthreads();

    const int wid = t >> 5, lane = t & 31;
    if (wid < 4) {
        const int i = i0 + wid;
        const int4* m4 = (const int4*)(mask + (b * NN + i) * NN);
        float4* s4 = (float4*)&s_attn[wid][0];
        int4 mv[4];
        float4 sv[4];
#pragma unroll
        for (int k = 0; k < 4; k++) {
            mv[k] = m4[lane + 32 * k];
            sv[k] = s4[lane + 32 * k];
        }
        float mx = -INFINITY;
#pragma unroll
        for (int k = 0; k < 4; k++) {
            if (mv[k].x) mx = fmaxf(mx, sv[k].x);
            if (mv[k].y) mx = fmaxf(mx, sv[k].y);
            if (mv[k].z) mx = fmaxf(mx, sv[k].z);
            if (mv[k].w) mx = fmaxf(mx, sv[k].w);
        }
#pragma unroll
        for (int o = 16; o; o >>= 1) mx = fmaxf(mx, __shfl_xor_sync(0xffffffffu, mx, o));
        float sum = 0.f;
#pragma unroll
        for (int k = 0; k < 4; k++) {
            sv[k].x = mv[k].x ? __expf(sv[k].x - mx) : 0.f;
            sv[k].y = mv[k].y ? __expf(sv[k].y - mx) : 0.f;
            sv[k].z = mv[k].z ? __expf(sv[k].z - mx) : 0.f;
            sv[k].w = mv[k].w ? __expf(sv[k].w - mx) : 0.f;
            sum += sv[k].x + sv[k].y + sv[k].z + sv[k].w;
        }
#pragma unroll
        for (int o = 16; o; o >>= 1) sum += __shfl_xor_sync(0xffffffffu, sum, o);
        const float inv = (sum > 0.f) ? 1.f / sum : 0.f;
        float4* arow4 = (float4*)(attn_out + (b * NN + i) * NN);
#pragma unroll
        for (int k = 0; k < 4; k++) {
            sv[k].x *= inv; sv[k].y *= inv; sv[k].z *= inv; sv[k].w *= inv;
            arow4[lane + 32 * k] = sv[k];
            const int jb = 4 * (lane + 32 * k);
            s_attn2[wid][jb + 0] = pack2(sv[k].x, sv[k].x);
            s_attn2[wid][jb + 1] = pack2(sv[k].y, sv[k].y);
            s_attn2[wid][jb + 2] = pack2(sv[k].z, sv[k].z);
            s_attn2[wid][jb + 3] = pack2(sv[k].w, sv[k].w);
        }
    }
    __syncthreads();

    // output GEMM (f32x2, 8 chains): thread -> col pair cp, j-group jg (64 j)
    {
        const int cp = t & 127;
        const int c2 = cp * 2;
        const int jg = t >> 7;
        ull o0A = 0, o1A = 0, o2A = 0, o3A = 0;   // h0 chains
        ull o0B = 0, o1B = 0, o2B = 0, o3B = 0;   // h1 chains
        const float* hb = g_h + b * NN * DM + c2;
        const int jb = jg * 64;
#pragma unroll 2
        for (int j = jb; j < jb + 64; j += 2) {
            ull h0 = *(const ull*)&hb[(j + 0) * DM];
            ull h1 = *(const ull*)&hb[(j + 1) * DM];
            ulonglong2 a0 = *(const ulonglong2*)&s_attn2[0][j];
            ulonglong2 a1 = *(const ulonglong2*)&s_attn2[1][j];
            ulonglong2 a2 = *(const ulonglong2*)&s_attn2[2][j];
            ulonglong2 a3 = *(const ulonglong2*)&s_attn2[3][j];
            o0A = fma2(a0.x, h0, o0A);  o0B = fma2(a0.y, h1, o0B);
            o1A = fma2(a1.x, h0, o1A);  o1B = fma2(a1.y, h1, o1B);
            o2A = fma2(a2.x, h0, o2A);  o2B = fma2(a2.y, h1, o2B);
            o3A = fma2(a3.x, h0, o3A);  o3B = fma2(a3.y, h1, o3B);
        }
        s_part[jg][0][cp] = add2(o0A, o0B);
        s_part[jg][1][cp] = add2(o1A, o1B);
        s_part[jg][2][cp] = add2(o2A, o2B);
        s_part[jg][3][cp] = add2(o3A, o3B);
    }
    __syncthreads();

    if (t < 512) {
        const int r = t >> 7;
        const int p = t & 127;
        ull s = s_part[0][r][p];
#pragma unroll
        for (int g = 1; g < 8; g++) s = add2(s, s_part[g][r][p]);
        *(ull*)&out[(b * NN + i0 + r) * DM + 2 * p] = s;
    }
}

// ---------------------------------------------------------------------------
extern "C" void kernel_launch(void* const* d_in, const int* in_sizes, int n_in,
                              void* d_out, int out_size) {
    const float* x    = (const float*)d_in[0];  // [2,512,512]
    const float* pos  = (const float*)d_in[1];  // [2,512,4]
    const int*   mask = (const int*)  d_in[2];  // [2,512,512]
    const float* Wx   = (const float*)d_in[3];  // [512,256]
    const float* bx   = (const float*)d_in[4];  // [256]
    const float* Wp   = (const float*)d_in[5];  // [4,256]
    const float* bp   = (const float*)d_in[6];  // [256]
    const float* w    = (const float*)d_in[7];  // [256]

    float* out      = (float*)d_out;            // [2,512,256]
    float* attn_out = out + BB * NN * DM;       // [2,512,512]

    kA<<<BB * NN / 4, 1024>>>(x, pos, Wx, bx, Wp, bp);
    kScore<<<(BB * NN / 4) * 4, 512>>>(w, attn_out);
    kSO<<<BB * NN / 4, 1024>>>(mask, out, attn_out);
}

// round 17
// speedup vs baseline: 1.0988x; 1.0988x over previous
#include <cuda_runtime.h>
#include <math.h>

#define BB 2
#define NN 512
#define DIN 512
#define DM 256
#define C2LOG2E 2.885390081777927f   // 2*log2(e)

typedef unsigned long long ull;

// scratch (static device globals — no allocation)
__device__ float g_h[BB * NN * DM];    // h[b][n][d] = tanh(x@Wx+bx)
__device__ float g_p[BB * NN * DM];    // P row-major: exp2(c*(u+bp))
__device__ float g_qt[BB * DM * NN];   // Q transposed: exp2(-c*u)[b][d][n]

__device__ __forceinline__ float ex2_fast(float x) {
    float y; asm("ex2.approx.f32 %0, %1;" : "=f"(y) : "f"(x)); return y;
}
__device__ __forceinline__ float rcp_fast(float x) {
    float y; asm("rcp.approx.f32 %0, %1;" : "=f"(y) : "f"(x)); return y;
}
// ---- packed f32x2 helpers (used ONLY in kScore — see R15/R16 post-mortems)
__device__ __forceinline__ ull pack2(float lo, float hi) {
    ull r; asm("mov.b64 %0, {%1, %2};" : "=l"(r) : "f"(lo), "f"(hi)); return r;
}
__device__ __forceinline__ void unpack2(ull v, float& lo, float& hi) {
    asm("mov.b64 {%0, %1}, %2;" : "=f"(lo), "=f"(hi) : "l"(v));
}
__device__ __forceinline__ ull fma2(ull a, ull b, ull c) {
    ull d; asm("fma.rn.f32x2 %0, %1, %2, %3;" : "=l"(d) : "l"(a), "l"(b), "l"(c)); return d;
}
__device__ __forceinline__ ull mul2(ull a, ull b) {
    ull d; asm("mul.rn.f32x2 %0, %1, %2;" : "=l"(d) : "l"(a), "l"(b)); return d;
}
__device__ __forceinline__ ull add2(ull a, ull b) {
    ull d; asm("add.rn.f32x2 %0, %1, %2;" : "=l"(d) : "l"(a), "l"(b)); return d;
}

// ---------------------------------------------------------------------------
// Kernel A (scalar, 8 rows/block): h = tanh(x @ Wx + bx), P/Q projections.
// grid = 128 blocks x 1024 threads: thread = (col c = t&255, K-quarter t>>8).
// Halves Wx L2 traffic vs 4-row version (64MB total).
// ---------------------------------------------------------------------------
__global__ __launch_bounds__(1024) void kA(const float* __restrict__ x,
                                           const float* __restrict__ pos,
                                           const float* __restrict__ Wx,
                                           const float* __restrict__ bx,
                                           const float* __restrict__ Wp,
                                           const float* __restrict__ bp) {
    __shared__ float s_x[DIN][8];          // 16KB, x tile transposed
    __shared__ float s_part[3][8][DM];     // 24KB, partials from kq=1..3
    const int t = threadIdx.x;
    const int row0 = blockIdx.x * 8;
    const int c  = t & (DM - 1);
    const int kq = t >> 8;                 // 0..3
    const int b = row0 / NN;
    const int n0 = row0 % NN;

    // pos projections (independent)
    if (t < DM) {
        const float w0 = Wp[0 * DM + t], w1 = Wp[1 * DM + t];
        const float w2 = Wp[2 * DM + t], w3 = Wp[3 * DM + t];
        const float bpv = bp[t];
#pragma unroll
        for (int r = 0; r < 8; r++) {
            const float* p = pos + (row0 + r) * 4;
            float u = p[0] * w0 + p[1] * w1 + p[2] * w2 + p[3] * w3;
            g_p[(row0 + r) * DM + t] = ex2_fast(C2LOG2E * (u + bpv));
            g_qt[(b * DM + t) * NN + n0 + r] = ex2_fast(-C2LOG2E * u);
        }
    }

    for (int e = t; e < DIN * 8; e += 1024) {
        int r = e >> 9, cc = e & (DIN - 1);
        s_x[cc][r] = x[(row0 + r) * DIN + cc];   // coalesced
    }
    __syncthreads();

    float a[8];
#pragma unroll
    for (int r = 0; r < 8; r++) a[r] = 0.f;
    const int kb = kq << 7;                // 128 k per quarter
#pragma unroll 4
    for (int k = 0; k < 128; k++) {
        float wv = Wx[(kb + k) * DM + c];              // coalesced, L2-hot
        float4 xA = *(const float4*)&s_x[kb + k][0];   // broadcast LDS.128
        float4 xB = *(const float4*)&s_x[kb + k][4];
        a[0] += xA.x * wv; a[1] += xA.y * wv;
        a[2] += xA.z * wv; a[3] += xA.w * wv;
        a[4] += xB.x * wv; a[5] += xB.y * wv;
        a[6] += xB.z * wv; a[7] += xB.w * wv;
    }
    if (kq) {
#pragma unroll
        for (int r = 0; r < 8; r++) s_part[kq - 1][r][c] = a[r];
    }
    __syncthreads();
    if (kq == 0) {
        const float bias = bx[c];
#pragma unroll
        for (int r = 0; r < 8; r++) {
            float s = a[r] + bias + s_part[0][r][c] + s_part[1][r][c] + s_part[2][r][c];
            g_h[(row0 + r) * DM + c] = tanhf(s);
        }
    }
}

// ---------------------------------------------------------------------------
// Kernel Score (R14 best, unchanged): f32x2 packed, 4 rows x 128 j per block,
// d split 8-way. grid = 1024 blocks, 512 threads.
// ---------------------------------------------------------------------------
__global__ __launch_bounds__(512) void kScore(const float* __restrict__ w,
                                              float* __restrict__ attn_out) {
    __shared__ ull s_pib[DM][4];        // P broadcast pairs, 8KB
    __shared__ ull s_wn2[DM];           // (-2w,-2w), 2KB
    __shared__ ull s_part[7][4][64];    // dq=1..7 partials, 14KB
    __shared__ float s_W;

    const int t   = threadIdx.x;
    const int tj2 = t & 63;
    const int dq  = t >> 6;
    const int jt  = blockIdx.x & 3;
    const int it  = blockIdx.x >> 2;
    const int b   = it / (NN / 4);
    const int i0  = (it % (NN / 4)) * 4;
    const int j0  = jt * 128 + tj2 * 2;

    if (t < DM) {
        float wv = -2.0f * w[t];
        s_wn2[t] = pack2(wv, wv);
    }
    if (t < 32) {
        float s = 0.f;
#pragma unroll
        for (int k = 0; k < 8; k++) s += w[t + 32 * k];
#pragma unroll
        for (int o = 16; o; o >>= 1) s += __shfl_xor_sync(0xffffffffu, s, o);
        if (t == 0) s_W = s;
    }
    {
        const float* prow = g_p + (b * NN + i0) * DM;
        for (int e = t; e < 4 * DM; e += 512) {
            int r = e >> 8, d = e & (DM - 1);
            float v = prow[r * DM + d];
            s_pib[d][r] = pack2(v, v);
        }
    }
    __syncthreads();

    const ull ONE2 = pack2(1.0f, 1.0f);
    ull acc0 = 0, acc1 = 0, acc2 = 0, acc3 = 0;
    const float* qp = g_qt + b * DM * NN + j0;
    const int db = dq << 5;
    ull qbuf[4];
#pragma unroll
    for (int p = 0; p < 4; p++) qbuf[p] = *(const ull*)(qp + (db + p) * NN);

    for (int d0 = db; d0 < db + 32; d0 += 4) {
        ull qc[4];
#pragma unroll
        for (int p = 0; p < 4; p++) qc[p] = qbuf[p];
        if (d0 + 4 < db + 32) {
#pragma unroll
            for (int p = 0; p < 4; p++) qbuf[p] = *(const ull*)(qp + (d0 + 4 + p) * NN);
        }
#pragma unroll
        for (int dd = 0; dd < 4; dd++) {
            const int d = d0 + dd;
            const ull wn2 = s_wn2[d];
            ulonglong2 piA = *(const ulonglong2*)&s_pib[d][0];
            ulonglong2 piB = *(const ulonglong2*)&s_pib[d][2];
            const ull qj2 = qc[dd];
            ull de0 = fma2(piA.x, qj2, ONE2);
            ull de1 = fma2(piA.y, qj2, ONE2);
            ull de2 = fma2(piB.x, qj2, ONE2);
            ull de3 = fma2(piB.y, qj2, ONE2);
            ull p01 = mul2(de0, de1);
            ull p23 = mul2(de2, de3);
            ull tot = mul2(p01, p23);
            float tl, th;
            unpack2(tot, tl, th);
            ull r2 = pack2(rcp_fast(tl), rcp_fast(th));
            ull i01 = mul2(r2, p23);
            ull i23 = mul2(r2, p01);
            ull w01 = mul2(wn2, i01);
            ull w23 = mul2(wn2, i23);
            acc0 = fma2(w01, de1, acc0);
            acc1 = fma2(w01, de0, acc1);
            acc2 = fma2(w23, de3, acc2);
            acc3 = fma2(w23, de2, acc3);
        }
    }
    if (dq) {
        s_part[dq - 1][0][tj2] = acc0;
        s_part[dq - 1][1][tj2] = acc1;
        s_part[dq - 1][2][tj2] = acc2;
        s_part[dq - 1][3][tj2] = acc3;
    }
    __syncthreads();
    if (dq == 0) {
        const ull W2 = pack2(s_W, s_W);
#pragma unroll
        for (int g = 0; g < 7; g++) {
            acc0 = add2(acc0, s_part[g][0][tj2]);
            acc1 = add2(acc1, s_part[g][1][tj2]);
            acc2 = add2(acc2, s_part[g][2][tj2]);
            acc3 = add2(acc3, s_part[g][3][tj2]);
        }
        float* arow = attn_out + (b * NN + i0) * NN + j0;
        *(ull*)&arow[0 * NN] = add2(acc0, W2);
        *(ull*)&arow[1 * NN] = add2(acc1, W2);
        *(ull*)&arow[2 * NN] = add2(acc2, W2);
        *(ull*)&arow[3 * NN] = add2(acc3, W2);
    }
}

// ---------------------------------------------------------------------------
// Kernel SO (R14 scalar best, reverted): masked softmax + output GEMM,
// thread owns 2 d-cols (float2 h), j split 8-way. grid 256 x 1024.
// ---------------------------------------------------------------------------
__global__ __launch_bounds__(1024) void kSO(const int* __restrict__ mask,
                                            float* __restrict__ out,
                                            float* __restrict__ attn_out) {
    __shared__ float s_attn[4][NN];      // 8KB
    __shared__ float s_part[8][4][DM];   // 32KB

    const int t = threadIdx.x;
    const int blk = blockIdx.x;
    const int b = blk / (NN / 4);
    const int i0 = (blk % (NN / 4)) * 4;

    {
        const float4* src = (const float4*)(attn_out + (b * NN + i0) * NN);
        float4* dst = (float4*)&s_attn[0][0];
        for (int e = t; e < 4 * NN / 4; e += 1024) dst[e] = src[e];
    }
    __syncthreads();

    const int wid = t >> 5, lane = t & 31;
    if (wid < 4) {
        const int i = i0 + wid;
        const int4* m4 = (const int4*)(mask + (b * NN + i) * NN);
        float4* s4 = (float4*)&s_attn[wid][0];
        int4 mv[4];
        float4 sv[4];
#pragma unroll
        for (int k = 0; k < 4; k++) {
            mv[k] = m4[lane + 32 * k];
            sv[k] = s4[lane + 32 * k];
        }
        float mx = -INFINITY;
#pragma unroll
        for (int k = 0; k < 4; k++) {
            if (mv[k].x) mx = fmaxf(mx, sv[k].x);
            if (mv[k].y) mx = fmaxf(mx, sv[k].y);
            if (mv[k].z) mx = fmaxf(mx, sv[k].z);
            if (mv[k].w) mx = fmaxf(mx, sv[k].w);
        }
#pragma unroll
        for (int o = 16; o; o >>= 1) mx = fmaxf(mx, __shfl_xor_sync(0xffffffffu, mx, o));
        float sum = 0.f;
#pragma unroll
        for (int k = 0; k < 4; k++) {
            sv[k].x = mv[k].x ? __expf(sv[k].x - mx) : 0.f;
            sv[k].y = mv[k].y ? __expf(sv[k].y - mx) : 0.f;
            sv[k].z = mv[k].z ? __expf(sv[k].z - mx) : 0.f;
            sv[k].w = mv[k].w ? __expf(sv[k].w - mx) : 0.f;
            sum += sv[k].x + sv[k].y + sv[k].z + sv[k].w;
        }
#pragma unroll
        for (int o = 16; o; o >>= 1) sum += __shfl_xor_sync(0xffffffffu, sum, o);
        const float inv = (sum > 0.f) ? 1.f / sum : 0.f;
        float4* arow4 = (float4*)(attn_out + (b * NN + i) * NN);
#pragma unroll
        for (int k = 0; k < 4; k++) {
            sv[k].x *= inv; sv[k].y *= inv; sv[k].z *= inv; sv[k].w *= inv;
            s4[lane + 32 * k] = sv[k];
            arow4[lane + 32 * k] = sv[k];
        }
    }
    __syncthreads();

    {
        const int c2 = (t & 127) * 2;
        const int jg = t >> 7;
        float o00 = 0.f, o01 = 0.f, o10 = 0.f, o11 = 0.f;
        float o20 = 0.f, o21 = 0.f, o30 = 0.f, o31 = 0.f;
        const float* hb = g_h + b * NN * DM + c2;
        const float4* p0 = (const float4*)&s_attn[0][0];
        const float4* p1 = (const float4*)&s_attn[1][0];
        const float4* p2 = (const float4*)&s_attn[2][0];
        const float4* p3 = (const float4*)&s_attn[3][0];
        const int j4b = jg * 16;
#pragma unroll 4
        for (int j4 = j4b; j4 < j4b + 16; j4++) {
            float2 h0 = *(const float2*)&hb[(4 * j4 + 0) * DM];
            float2 h1 = *(const float2*)&hb[(4 * j4 + 1) * DM];
            float2 h2 = *(const float2*)&hb[(4 * j4 + 2) * DM];
            float2 h3 = *(const float2*)&hb[(4 * j4 + 3) * DM];
            float4 a0 = p0[j4];
            float4 a1 = p1[j4];
            float4 a2 = p2[j4];
            float4 a3 = p3[j4];
            o00 += a0.x * h0.x + a0.y * h1.x + a0.z * h2.x + a0.w * h3.x;
            o01 += a0.x * h0.y + a0.y * h1.y + a0.z * h2.y + a0.w * h3.y;
            o10 += a1.x * h0.x + a1.y * h1.x + a1.z * h2.x + a1.w * h3.x;
            o11 += a1.x * h0.y + a1.y * h1.y + a1.z * h2.y + a1.w * h3.y;
            o20 += a2.x * h0.x + a2.y * h1.x + a2.z * h2.x + a2.w * h3.x;
            o21 += a2.x * h0.y + a2.y * h1.y + a2.z * h2.y + a2.w * h3.y;
            o30 += a3.x * h0.x + a3.y * h1.x + a3.z * h2.x + a3.w * h3.x;
            o31 += a3.x * h0.y + a3.y * h1.y + a3.z * h2.y + a3.w * h3.y;
        }
        s_part[jg][0][c2] = o00; s_part[jg][0][c2 + 1] = o01;
        s_part[jg][1][c2] = o10; s_part[jg][1][c2 + 1] = o11;
        s_part[jg][2][c2] = o20; s_part[jg][2][c2 + 1] = o21;
        s_part[jg][3][c2] = o30; s_part[jg][3][c2 + 1] = o31;
    }
    __syncthreads();

    {
        const int r = t >> 8;
        const int d = t & (DM - 1);
        float s = 0.f;
#pragma unroll
        for (int g = 0; g < 8; g++) s += s_part[g][r][d];
        out[(b * NN + i0 + r) * DM + d] = s;
    }
}

// ---------------------------------------------------------------------------
extern "C" void kernel_launch(void* const* d_in, const int* in_sizes, int n_in,
                              void* d_out, int out_size) {
    const float* x    = (const float*)d_in[0];  // [2,512,512]
    const float* pos  = (const float*)d_in[1];  // [2,512,4]
    const int*   mask = (const int*)  d_in[2];  // [2,512,512]
    const float* Wx   = (const float*)d_in[3];  // [512,256]
    const float* bx   = (const float*)d_in[4];  // [256]
    const float* Wp   = (const float*)d_in[5];  // [4,256]
    const float* bp   = (const float*)d_in[6];  // [256]
    const float* w    = (const float*)d_in[7];  // [256]

    float* out      = (float*)d_out;            // [2,512,256]
    float* attn_out = out + BB * NN * DM;       // [2,512,512]

    kA<<<BB * NN / 8, 1024>>>(x, pos, Wx, bx, Wp, bp);
    kScore<<<(BB * NN / 4) * 4, 512>>>(w, attn_out);
    kSO<<<BB * NN / 4, 1024>>>(mask, out, attn_out);
}